// round 15
// baseline (speedup 1.0000x reference)
#include <cuda_runtime.h>
#include <cuda_bf16.h>

// out[b,d,n] = w[d] * in[b,d,n];  B=8, D=2048, N=2048, fp32.
// R15: UNROLL=16 probe along the confirmed MLP gradient (4->8 recovered
// DRAM 69.7->74.5% in the slow-clock session). 16 front-batched independent
// LDG.128 per thread; ~80-90 regs, occ ~50% (ample: issue=7.6%).
// Exact-cover grid, weights (8KB) L2-resident via __ldg.

static constexpr int B = 8;
static constexpr int D = 2048;
static constexpr int N = 2048;
static constexpr long long TOTAL4 = (long long)B * D * N / 4;  // 8,388,608 float4
static constexpr int THREADS = 256;
static constexpr int UNROLL  = 16;
static constexpr int BLOCK_ELEMS = THREADS * UNROLL;           // 4096 float4 / block

__global__ void __launch_bounds__(THREADS)
channel_scale_kernel(const float4* __restrict__ in,
                     const float*  __restrict__ w,
                     float4*       __restrict__ out)
{
    long long base = (long long)blockIdx.x * BLOCK_ELEMS + threadIdx.x;

    // Front-batch all loads: 16 independent LDG.128 in flight per thread.
    float4 v[UNROLL];
#pragma unroll
    for (int k = 0; k < UNROLL; k++) {
        v[k] = in[base + (long long)k * THREADS];
    }

#pragma unroll
    for (int k = 0; k < UNROLL; k++) {
        long long i = base + (long long)k * THREADS;
        // channel index: i4 / (N/4) % D ; N/4 = 512, D = 2048
        int d = (int)((i >> 9) & (D - 1));
        float s = __ldg(w + d);          // L1/L2 resident (8 KB)
        v[k].x *= s; v[k].y *= s; v[k].z *= s; v[k].w *= s;
        out[i] = v[k];
    }
}

extern "C" void kernel_launch(void* const* d_in, const int* in_sizes, int n_in,
                              void* d_out, int out_size)
{
    const float4* in = (const float4*)d_in[0];   // inputs [B, D, N] fp32
    const float*  w  = (const float*)d_in[1];    // attention_weights [D] fp32
    float4* out = (float4*)d_out;

    long long blocks = TOTAL4 / BLOCK_ELEMS;     // 2048, exact cover
    channel_scale_kernel<<<(unsigned)blocks, THREADS>>>(in, w, out);
}

// round 17
// speedup vs baseline: 1.0114x; 1.0114x over previous
#include <cuda_runtime.h>
#include <cuda_bf16.h>

// out[b,d,n] = w[d] * in[b,d,n];  B=8, D=2048, N=2048, fp32.
// FINAL (= R14, the empirical optimum of the full sweep):
//   unroll: 4 < 8 > 16  (16 forced ptxas to drop front-batching, regs=32)
//   access: LDG.128 = LDG.256; .cs hints neutral; TMA bulk store worse
//   tiling: 1/2/7-wave all equal; smem staging worse
// HBM-bound at the B300 R/W-mix DRAM ceiling (~5.9 TB/s; session clock state
// moves the band 69-76%). 8 front-batched independent LDG.128 per thread,
// plain STG.128, exact-cover grid, weights (8KB) L2-resident via __ldg.
// Best recorded: 36.1us kernel / 74.5% DRAM (this config, slow session);
// 35.6us kernel / 43.5us wall (equivalent config, fast session).

static constexpr int B = 8;
static constexpr int D = 2048;
static constexpr int N = 2048;
static constexpr long long TOTAL4 = (long long)B * D * N / 4;  // 8,388,608 float4
static constexpr int THREADS = 256;
static constexpr int UNROLL  = 8;
static constexpr int BLOCK_ELEMS = THREADS * UNROLL;           // 2048 float4 / block

__global__ void __launch_bounds__(THREADS)
channel_scale_kernel(const float4* __restrict__ in,
                     const float*  __restrict__ w,
                     float4*       __restrict__ out)
{
    long long base = (long long)blockIdx.x * BLOCK_ELEMS + threadIdx.x;

    // Front-batch all loads: 8 independent LDG.128 in flight per thread.
    float4 v[UNROLL];
#pragma unroll
    for (int k = 0; k < UNROLL; k++) {
        v[k] = in[base + (long long)k * THREADS];
    }

#pragma unroll
    for (int k = 0; k < UNROLL; k++) {
        long long i = base + (long long)k * THREADS;
        // channel index: i4 / (N/4) % D ; N/4 = 512, D = 2048
        int d = (int)((i >> 9) & (D - 1));
        float s = __ldg(w + d);          // L1/L2 resident (8 KB)
        v[k].x *= s; v[k].y *= s; v[k].z *= s; v[k].w *= s;
        out[i] = v[k];
    }
}

extern "C" void kernel_launch(void* const* d_in, const int* in_sizes, int n_in,
                              void* d_out, int out_size)
{
    const float4* in = (const float4*)d_in[0];   // inputs [B, D, N] fp32
    const float*  w  = (const float*)d_in[1];    // attention_weights [D] fp32
    float4* out = (float4*)d_out;

    long long blocks = TOTAL4 / BLOCK_ELEMS;     // 4096, exact cover
    channel_scale_kernel<<<(unsigned)blocks, THREADS>>>(in, w, out);
}